// round 14
// baseline (speedup 1.0000x reference)
#include <cuda_runtime.h>
#include <cstdint>

// Zero-initialized at module load; the last-ticket block resets it to zero at
// the end of every call, so no per-call memset node is needed (1-node graph).
struct State { double acc; unsigned long long count; };
__device__ State g_state;   // static init = {0, 0}

static constexpr int BLOCKS  = 444;    // 3 blocks/SM resident (80 regs), persistent
static constexpr int THREADS = 256;    // 8 warps/block
static constexpr int WARPS_TOTAL = BLOCKS * (THREADS / 32);

// R13 body with ONE change: default-policy loads (__ldg) instead of __ldcs.
// Rows are 4000B (not 128B-aligned); adjacent rows share a boundary L2 line
// and are streamed by adjacent (concurrent) warps -> default policy lets L2
// serve the shared line instead of evict-first dropping it.
__global__ __launch_bounds__(THREADS)
void cosine_loss_kernel(const float* __restrict__ logits,
                        const int* __restrict__ labels,
                        int N, int C, float* __restrict__ out, double inv_n) {
    const int lane  = threadIdx.x & 31;
    const int warp_in_block = threadIdx.x >> 5;
    const int gwarp = blockIdx.x * (THREADS >> 5) + warp_in_block;

    double local = 0.0;

    int row = gwarp;
    float4 v[8];
    int lab = 0;

    // Prologue: loads for the first row.
    if (row < N) {
        const float4* __restrict__ row4 =
            reinterpret_cast<const float4*>(logits + (size_t)row * (size_t)C);
        lab = __ldg(labels + row);
        #pragma unroll
        for (int k = 0; k < 7; k++)
            v[k] = __ldg(row4 + lane + 32 * k);
        v[7] = make_float4(0.f, 0.f, 0.f, 0.f);
        if (lane < 26)
            v[7] = __ldg(row4 + lane + 224);
    }

    while (row < N) {
        // Snapshot current row, then issue next row's loads immediately.
        float4 cur[8];
        #pragma unroll
        for (int k = 0; k < 8; k++) cur[k] = v[k];
        const int labc = lab;

        const int next = row + WARPS_TOTAL;
        if (next < N) {
            const float4* __restrict__ row4 =
                reinterpret_cast<const float4*>(logits + (size_t)next * (size_t)C);
            lab = __ldg(labels + next);
            #pragma unroll
            for (int k = 0; k < 7; k++)
                v[k] = __ldg(row4 + lane + 32 * k);
            v[7] = make_float4(0.f, 0.f, 0.f, 0.f);
            if (lane < 26)
                v[7] = __ldg(row4 + lane + 224);
        }

        // Reduce current row; extract the label component in-pass.
        const int j4   = labc >> 2;          // float4 index within row [0,250)
        const int comp = labc & 3;
        const int lane_owner = j4 & 31;

        float s = 0.0f;
        float dot_l = 0.0f;
        #pragma unroll
        for (int k = 0; k < 8; k++) {
            if (j4 == lane + 32 * k) {
                dot_l = (comp == 0) ? cur[k].x :
                        (comp == 1) ? cur[k].y :
                        (comp == 2) ? cur[k].z : cur[k].w;
            }
            s = fmaf(cur[k].x, cur[k].x, s);
            s = fmaf(cur[k].y, cur[k].y, s);
            s = fmaf(cur[k].z, cur[k].z, s);
            s = fmaf(cur[k].w, cur[k].w, s);
        }
        #pragma unroll
        for (int o = 16; o > 0; o >>= 1)
            s += __shfl_xor_sync(0xFFFFFFFFu, s, o);
        const float dot = __shfl_sync(0xFFFFFFFFu, dot_l, lane_owner);

        if (lane == 0) {
            const float cosv = dot / fmaxf(sqrtf(s), 1e-8f);
            local += 1.0 - (double)cosv;
        }

        row = next;
    }

    // Block reduction, once per block.
    __shared__ double sh[THREADS >> 5];
    if (lane == 0) sh[warp_in_block] = local;
    __syncthreads();

    if (threadIdx.x == 0) {
        double t = 0.0;
        #pragma unroll
        for (int i = 0; i < (THREADS >> 5); i++) t += sh[i];
        atomicAdd(&g_state.acc, t);

        __threadfence();
        unsigned long long ticket = atomicAdd(&g_state.count, 1ULL);
        if (ticket == (unsigned long long)gridDim.x - 1ULL) {
            // All gridDim.x accumulations are complete (ticket order).
            double acc = *(volatile double*)&g_state.acc;
            *out = (float)(acc * inv_n);
            // Self-reset so the next call starts from a zeroed state:
            // no memset node needed -> 1-node graph.
            g_state.acc = 0.0;
            __threadfence();
            g_state.count = 0ULL;
        }
    }
}

extern "C" void kernel_launch(void* const* d_in, const int* in_sizes, int n_in,
                              void* d_out, int out_size) {
    const float* logits = (const float*)d_in[0];
    const int*   labels = (const int*)d_in[1];
    float* out = (float*)d_out;

    const int N = in_sizes[1];          // rows == labels
    const int C = in_sizes[0] / N;      // 1000

    cosine_loss_kernel<<<BLOCKS, THREADS>>>(logits, labels, N, C, out,
                                            1.0 / (double)N);
}

// round 15
// speedup vs baseline: 1.0008x; 1.0008x over previous
#include <cuda_runtime.h>
#include <cstdint>

// Zero-initialized at module load; the last-ticket block resets it to zero at
// the end of every call, so no per-call memset node is needed (1-node graph).
struct State { double acc; unsigned long long count; };
__device__ State g_state;   // static init = {0, 0}

static constexpr int BLOCKS  = 444;    // 3 blocks/SM resident (80 regs), persistent
static constexpr int THREADS = 256;    // 8 warps/block
static constexpr int WARPS_TOTAL = BLOCKS * (THREADS / 32);

// Final kernel: software-pipelined persistent warps (snapshot double-buffer),
// in-pass label extraction (no gather load), default-policy loads (rows are
// 4000B so adjacent concurrent warps share boundary L2 lines), block reduce +
// one double atomic per block, last-ticket fused finalize + self-reset.
__global__ __launch_bounds__(THREADS)
void cosine_loss_kernel(const float* __restrict__ logits,
                        const int* __restrict__ labels,
                        int N, int C, float* __restrict__ out, double inv_n) {
    const int lane  = threadIdx.x & 31;
    const int warp_in_block = threadIdx.x >> 5;
    const int gwarp = blockIdx.x * (THREADS >> 5) + warp_in_block;

    double local = 0.0;

    int row = gwarp;
    float4 v[8];
    int lab = 0;

    // Prologue: loads for the first row.
    if (row < N) {
        const float4* __restrict__ row4 =
            reinterpret_cast<const float4*>(logits + (size_t)row * (size_t)C);
        lab = __ldg(labels + row);
        #pragma unroll
        for (int k = 0; k < 7; k++)
            v[k] = __ldg(row4 + lane + 32 * k);
        v[7] = make_float4(0.f, 0.f, 0.f, 0.f);
        if (lane < 26)
            v[7] = __ldg(row4 + lane + 224);
    }

    while (row < N) {
        // Snapshot current row, then issue next row's loads immediately.
        float4 cur[8];
        #pragma unroll
        for (int k = 0; k < 8; k++) cur[k] = v[k];
        const int labc = lab;

        const int next = row + WARPS_TOTAL;
        if (next < N) {
            const float4* __restrict__ row4 =
                reinterpret_cast<const float4*>(logits + (size_t)next * (size_t)C);
            lab = __ldg(labels + next);
            #pragma unroll
            for (int k = 0; k < 7; k++)
                v[k] = __ldg(row4 + lane + 32 * k);
            v[7] = make_float4(0.f, 0.f, 0.f, 0.f);
            if (lane < 26)
                v[7] = __ldg(row4 + lane + 224);
        }

        // Reduce current row; extract the label component in-pass.
        const int j4   = labc >> 2;          // float4 index within row [0,250)
        const int comp = labc & 3;
        const int lane_owner = j4 & 31;

        float s = 0.0f;
        float dot_l = 0.0f;
        #pragma unroll
        for (int k = 0; k < 8; k++) {
            if (j4 == lane + 32 * k) {
                dot_l = (comp == 0) ? cur[k].x :
                        (comp == 1) ? cur[k].y :
                        (comp == 2) ? cur[k].z : cur[k].w;
            }
            s = fmaf(cur[k].x, cur[k].x, s);
            s = fmaf(cur[k].y, cur[k].y, s);
            s = fmaf(cur[k].z, cur[k].z, s);
            s = fmaf(cur[k].w, cur[k].w, s);
        }
        #pragma unroll
        for (int o = 16; o > 0; o >>= 1)
            s += __shfl_xor_sync(0xFFFFFFFFu, s, o);
        const float dot = __shfl_sync(0xFFFFFFFFu, dot_l, lane_owner);

        if (lane == 0) {
            const float cosv = dot / fmaxf(sqrtf(s), 1e-8f);
            local += 1.0 - (double)cosv;
        }

        row = next;
    }

    // Block reduction, once per block.
    __shared__ double sh[THREADS >> 5];
    if (lane == 0) sh[warp_in_block] = local;
    __syncthreads();

    if (threadIdx.x == 0) {
        double t = 0.0;
        #pragma unroll
        for (int i = 0; i < (THREADS >> 5); i++) t += sh[i];
        atomicAdd(&g_state.acc, t);

        __threadfence();
        unsigned long long ticket = atomicAdd(&g_state.count, 1ULL);
        if (ticket == (unsigned long long)gridDim.x - 1ULL) {
            // All gridDim.x accumulations are complete (ticket order).
            double acc = *(volatile double*)&g_state.acc;
            *out = (float)(acc * inv_n);
            // Self-reset so the next call starts from a zeroed state:
            // no memset node needed -> 1-node graph.
            g_state.acc = 0.0;
            __threadfence();
            g_state.count = 0ULL;
        }
    }
}

extern "C" void kernel_launch(void* const* d_in, const int* in_sizes, int n_in,
                              void* d_out, int out_size) {
    const float* logits = (const float*)d_in[0];
    const int*   labels = (const int*)d_in[1];
    float* out = (float*)d_out;

    const int N = in_sizes[1];          // rows == labels
    const int C = in_sizes[0] / N;      // 1000

    cosine_loss_kernel<<<BLOCKS, THREADS>>>(logits, labels, N, C, out,
                                            1.0 / (double)N);
}

// round 16
// speedup vs baseline: 1.0212x; 1.0204x over previous
#include <cuda_runtime.h>
#include <cstdint>

// Zero-initialized at module load; the last-ticket block resets it to zero at
// the end of every call, so no per-call memset node is needed (1-node graph).
struct State { double acc; unsigned long long count; };
__device__ State g_state;   // static init = {0, 0}

static constexpr int BLOCKS  = 444;    // 3 blocks/SM resident (80 regs), persistent
static constexpr int THREADS = 256;    // 8 warps/block
static constexpr int WARPS_TOTAL = BLOCKS * (THREADS / 32);

// Final kernel (converged at ~97% of the LTS stream ceiling):
//  - persistent warps, one row per warp per step, software-pipelined with a
//    snapshot double-buffer (next row's 8 float4 loads issue before the
//    current row's reduce tail),
//  - label component extracted in-pass from the streamed float4s (no gather),
//  - default-policy loads (4000B rows share boundary L2 lines across
//    adjacent concurrent warps; evict-first measured slower),
//  - block reduce + one double atomic per block,
//  - last-ticket fused finalize + self-reset -> 1-node graph.
__global__ __launch_bounds__(THREADS)
void cosine_loss_kernel(const float* __restrict__ logits,
                        const int* __restrict__ labels,
                        int N, int C, float* __restrict__ out, double inv_n) {
    const int lane  = threadIdx.x & 31;
    const int warp_in_block = threadIdx.x >> 5;
    const int gwarp = blockIdx.x * (THREADS >> 5) + warp_in_block;

    double local = 0.0;

    int row = gwarp;
    float4 v[8];
    int lab = 0;

    // Prologue: loads for the first row.
    if (row < N) {
        const float4* __restrict__ row4 =
            reinterpret_cast<const float4*>(logits + (size_t)row * (size_t)C);
        lab = __ldg(labels + row);
        #pragma unroll
        for (int k = 0; k < 7; k++)
            v[k] = __ldg(row4 + lane + 32 * k);
        v[7] = make_float4(0.f, 0.f, 0.f, 0.f);
        if (lane < 26)
            v[7] = __ldg(row4 + lane + 224);
    }

    while (row < N) {
        // Snapshot current row, then issue next row's loads immediately.
        float4 cur[8];
        #pragma unroll
        for (int k = 0; k < 8; k++) cur[k] = v[k];
        const int labc = lab;

        const int next = row + WARPS_TOTAL;
        if (next < N) {
            const float4* __restrict__ row4 =
                reinterpret_cast<const float4*>(logits + (size_t)next * (size_t)C);
            lab = __ldg(labels + next);
            #pragma unroll
            for (int k = 0; k < 7; k++)
                v[k] = __ldg(row4 + lane + 32 * k);
            v[7] = make_float4(0.f, 0.f, 0.f, 0.f);
            if (lane < 26)
                v[7] = __ldg(row4 + lane + 224);
        }

        // Reduce current row; extract the label component in-pass.
        const int j4   = labc >> 2;          // float4 index within row [0,250)
        const int comp = labc & 3;
        const int lane_owner = j4 & 31;

        float s = 0.0f;
        float dot_l = 0.0f;
        #pragma unroll
        for (int k = 0; k < 8; k++) {
            if (j4 == lane + 32 * k) {
                dot_l = (comp == 0) ? cur[k].x :
                        (comp == 1) ? cur[k].y :
                        (comp == 2) ? cur[k].z : cur[k].w;
            }
            s = fmaf(cur[k].x, cur[k].x, s);
            s = fmaf(cur[k].y, cur[k].y, s);
            s = fmaf(cur[k].z, cur[k].z, s);
            s = fmaf(cur[k].w, cur[k].w, s);
        }
        #pragma unroll
        for (int o = 16; o > 0; o >>= 1)
            s += __shfl_xor_sync(0xFFFFFFFFu, s, o);
        const float dot = __shfl_sync(0xFFFFFFFFu, dot_l, lane_owner);

        if (lane == 0) {
            const float cosv = dot / fmaxf(sqrtf(s), 1e-8f);
            local += 1.0 - (double)cosv;
        }

        row = next;
    }

    // Block reduction, once per block.
    __shared__ double sh[THREADS >> 5];
    if (lane == 0) sh[warp_in_block] = local;
    __syncthreads();

    if (threadIdx.x == 0) {
        double t = 0.0;
        #pragma unroll
        for (int i = 0; i < (THREADS >> 5); i++) t += sh[i];
        atomicAdd(&g_state.acc, t);

        __threadfence();
        unsigned long long ticket = atomicAdd(&g_state.count, 1ULL);
        if (ticket == (unsigned long long)gridDim.x - 1ULL) {
            // All gridDim.x accumulations are complete (ticket order).
            double acc = *(volatile double*)&g_state.acc;
            *out = (float)(acc * inv_n);
            // Self-reset so the next call starts from a zeroed state:
            // no memset node needed -> 1-node graph.
            g_state.acc = 0.0;
            __threadfence();
            g_state.count = 0ULL;
        }
    }
}

extern "C" void kernel_launch(void* const* d_in, const int* in_sizes, int n_in,
                              void* d_out, int out_size) {
    const float* logits = (const float*)d_in[0];
    const int*   labels = (const int*)d_in[1];
    float* out = (float*)d_out;

    const int N = in_sizes[1];          // rows == labels
    const int C = in_sizes[0] / N;      // 1000

    cosine_loss_kernel<<<BLOCKS, THREADS>>>(logits, labels, N, C, out,
                                            1.0 / (double)N);
}